// round 5
// baseline (speedup 1.0000x reference)
#include <cuda_runtime.h>
#include <cuda_fp16.h>
#include <cstdint>

#define NB     131072
#define ND     256
#define NTILES 1024          // NB / 128
#define GRID   152
#define NTHR   512
#define RS     528           // smem row stride bytes (256 f16 + 8 pad) = odd*16

// dynamic smem layout
#define OFF_A   0                    // 128 rows * 528 B = 67584
#define OFF_B   67584                // 256 rows * 528 B = 135168
#define OFF_W   (67584 + 135168)     // 16 rows * 528 B = 8448
#define DYN_SMEM (67584 + 135168 + 8448)   // 211200

// ---------------- device scratch (static; no cudaMalloc) ------------------
__device__ __align__(128) __half g_Wd_img[3][256 * 264];  // pre-padded smem image
__device__ __align__(128) __half g_Wout_img[16 * 264];
__device__ float g_bias[3][256];
__device__ float g_bout[16];

// ---------------- helpers -------------------------------------------------
static __device__ __forceinline__ uint32_t smem_u32(const void* p) {
    uint32_t a;
    asm("{ .reg .u64 t; cvta.to.shared.u64 t, %1; cvt.u32.u64 %0, t; }" : "=r"(a) : "l"(p));
    return a;
}

static __device__ __forceinline__ void ldsm4(uint32_t r[4], uint32_t addr) {
    asm volatile("ldmatrix.sync.aligned.m8n8.x4.shared.b16 {%0,%1,%2,%3}, [%4];"
                 : "=r"(r[0]), "=r"(r[1]), "=r"(r[2]), "=r"(r[3]) : "r"(addr));
}

static __device__ __forceinline__ void mma16816(float c[4], const uint32_t a[4],
                                                const uint32_t b[2]) {
    asm volatile("mma.sync.aligned.m16n8k16.row.col.f32.f16.f16.f32 "
                 "{%0,%1,%2,%3}, {%4,%5,%6,%7}, {%8,%9}, {%0,%1,%2,%3};"
                 : "+f"(c[0]), "+f"(c[1]), "+f"(c[2]), "+f"(c[3])
                 : "r"(a[0]), "r"(a[1]), "r"(a[2]), "r"(a[3]), "r"(b[0]), "r"(b[1]));
}

// exact-enough tanh: (e^{2z}-1)/(e^{2z}+1) via ex2/rcp MUFU, err ~1e-6.
static __device__ __forceinline__ float tanh_ex(float z) {
    float t, r;
    asm("ex2.approx.f32 %0, %1;" : "=f"(t) : "f"(z * 2.885390081777927f)); // 2*log2(e)
    asm("rcp.approx.f32 %0, %1;" : "=f"(r) : "f"(t + 1.0f));
    return (t - 1.0f) * r;
}

#define CP_ASYNC16(dst, src) \
    asm volatile("cp.async.cg.shared.global [%0], [%1], 16;" :: "r"(dst), "l"(src) : "memory")
#define CP_COMMIT() asm volatile("cp.async.commit_group;" ::: "memory")
#define CP_WAIT0()  asm volatile("cp.async.wait_group 0;" ::: "memory")

// ---------------- merged prep kernel --------------------------------------
__global__ void prep_kernel(const int* __restrict__ idx, const float* __restrict__ W,
                            const float* __restrict__ W_out, const float* __restrict__ b,
                            const float* __restrict__ b_out) {
    int blk = blockIdx.x;
    int t = threadIdx.x;                    // 256 = d
    if (blk < 768) {
        __shared__ int   s_i[128];
        __shared__ float s_w[128];
        int l = blk >> 8, n = blk & 255, g = n >> 6, u = n & 63;
        if (t < 128) {
            s_i[t] = idx[(l * 4 + g) * 128 + t];
            s_w[t] = W[((l * 4 + g) * 128 + t) * 64 + u];
        }
        __syncthreads();
        float sum = 0.0f;
#pragma unroll 8
        for (int k = 0; k < 128; k++)
            if (s_i[k] == t) sum += s_w[k];
        g_Wd_img[l][n * 264 + t] = __float2half(sum);
    } else {
#pragma unroll
        for (int j = 0; j < 16; j++)
            g_Wout_img[j * 264 + t] = __float2half(j < 10 ? W_out[t * 10 + j] : 0.0f);
        for (int l = 0; l < 3; l++)
            g_bias[l][t] = b[(l * 4 + (t >> 6)) * 64 + (t & 63)];
        if (t < 16) g_bout[t] = (t < 10) ? b_out[t] : 0.0f;
    }
}

// ---------------- main fused kernel ---------------------------------------
__global__ __launch_bounds__(NTHR, 1)
void fused_kernel(const float* __restrict__ x, float* __restrict__ out) {
    extern __shared__ __align__(16) char dsm[];
    char* pA = dsm + OFF_A;
    uint32_t sA = smem_u32(dsm) + OFF_A;
    uint32_t sB = smem_u32(dsm) + OFF_B;
    uint32_t sW = smem_u32(dsm) + OFF_W;

    __shared__ float s_bias[3][256];
    __shared__ float s_bout[16];

    int tid = threadIdx.x, wid = tid >> 5, lane = tid & 31;
    int lrow = lane & 7, sub = lane >> 3;
    uint32_t a_off = (uint32_t)((lrow + 8 * (sub & 1)) * RS + (sub >> 1) * 16);
    uint32_t b_off = (uint32_t)((lrow + 8 * (sub >> 1)) * RS + (sub & 1) * 16);

    int m0 = (wid >> 3) * 64;   // warp M-origin (0 or 64)
    int n0 = (wid & 7) * 32;    // warp N-origin (0..224)

    // ---- one-time: biases, Wout image, B0 image --------------------------
    if (tid < 256) {
        s_bias[0][tid] = g_bias[0][tid];
        s_bias[1][tid] = g_bias[1][tid];
        s_bias[2][tid] = g_bias[2][tid];
        if (tid < 16) s_bout[tid] = g_bout[tid];
    }
    {
        const char* wsrc = (const char*)g_Wout_img;
        for (int c = tid; c < 528; c += NTHR)            // 8448 B
            CP_ASYNC16(sW + c * 16, wsrc + c * 16);
        const char* bsrc = (const char*)g_Wd_img[0];
        for (int c = tid; c < 8448; c += NTHR)           // 135168 B
            CP_ASYNC16(sB + c * 16, bsrc + c * 16);
        CP_COMMIT();
        CP_WAIT0();
    }
    __syncthreads();

    for (int t = blockIdx.x; t < NTILES; t += GRID) {
        // ---- load x tile -> f16 padded A smem ---------------------------
        const float* xt = x + (size_t)t * 128 * ND;
#pragma unroll
        for (int i = 0; i < 8; i++) {
            int chunk = tid + i * NTHR;                  // 4096 chunks of 8 f16
            int row = chunk >> 5, k16 = chunk & 31;
            const float4* p = (const float4*)(xt + row * ND + k16 * 8);
            float4 a = p[0], bq = p[1];
            __half2 h0 = __floats2half2_rn(a.x, a.y);
            __half2 h1 = __floats2half2_rn(a.z, a.w);
            __half2 h2 = __floats2half2_rn(bq.x, bq.y);
            __half2 h3 = __floats2half2_rn(bq.z, bq.w);
            *(uint4*)(pA + row * RS + k16 * 16) =
                make_uint4(*(uint32_t*)&h0, *(uint32_t*)&h1,
                           *(uint32_t*)&h2, *(uint32_t*)&h3);
        }
        __syncthreads();

        // ---- 3 fused levels --------------------------------------------
        for (int l = 0; l < 3; l++) {
            // GEMM: C[128x256] = A[128x256] @ Wd[l]^T  (per-warp 64x32)
            float c[4][4][4];
#pragma unroll
            for (int mt = 0; mt < 4; mt++)
#pragma unroll
                for (int nt = 0; nt < 4; nt++)
#pragma unroll
                    for (int q = 0; q < 4; q++) c[mt][nt][q] = 0.0f;

#pragma unroll 4
            for (int kc = 0; kc < 16; kc++) {
                uint32_t a[4][4], b[2][4];
#pragma unroll
                for (int mt = 0; mt < 4; mt++)
                    ldsm4(a[mt], sA + (uint32_t)((m0 + 16 * mt) * RS + kc * 32) + a_off);
#pragma unroll
                for (int bt = 0; bt < 2; bt++)
                    ldsm4(b[bt], sB + (uint32_t)((n0 + 16 * bt) * RS + kc * 32) + b_off);
#pragma unroll
                for (int mt = 0; mt < 4; mt++)
#pragma unroll
                    for (int nt = 0; nt < 4; nt++)
                        mma16816(c[mt][nt], a[mt], &b[nt >> 1][(nt & 1) * 2]);
            }
            __syncthreads();   // all warps done reading A and B[l]

            // prefetch next B image (l+1; at l==2 prefetch B0 for next tile)
            {
                const char* bsrc = (const char*)g_Wd_img[(l == 2) ? 0 : (l + 1)];
                for (int cc = tid; cc < 8448; cc += NTHR)
                    CP_ASYNC16(sB + cc * 16, bsrc + cc * 16);
                CP_COMMIT();
            }

            // epilogue: bias + exact tanh -> f16, write h back into A.
            const float* bias = s_bias[l];
#pragma unroll
            for (int mt = 0; mt < 4; mt++) {
                int row = m0 + 16 * mt + (lane >> 2);
#pragma unroll
                for (int nt = 0; nt < 4; nt++) {
                    int n = n0 + 8 * nt + 2 * (lane & 3);
                    float b0v = bias[n], b1v = bias[n + 1];
                    float y0 = tanh_ex(c[mt][nt][0] + b0v);
                    float y1 = tanh_ex(c[mt][nt][1] + b1v);
                    float y2 = tanh_ex(c[mt][nt][2] + b0v);
                    float y3 = tanh_ex(c[mt][nt][3] + b1v);
                    __half2 h01 = __floats2half2_rn(y0, y1);
                    __half2 h23 = __floats2half2_rn(y2, y3);
                    *(uint32_t*)(pA + row * RS + n * 2)       = *(uint32_t*)&h01;
                    *(uint32_t*)(pA + (row + 8) * RS + n * 2) = *(uint32_t*)&h23;
                }
            }
            CP_WAIT0();
            __syncthreads();   // h visible + next B visible
        }

        // ---- final layer: out = h3 @ W_out + b_out (8 warps, 16 rows ea) -
        if (wid < 8) {
            float cf[2][4];
#pragma unroll
            for (int nt = 0; nt < 2; nt++)
#pragma unroll
                for (int q = 0; q < 4; q++) cf[nt][q] = 0.0f;
            int m0f = wid * 16;
#pragma unroll
            for (int kc = 0; kc < 16; kc++) {
                uint32_t a[4], b[4];
                ldsm4(a, sA + (uint32_t)(m0f * RS + kc * 32) + a_off);
                ldsm4(b, sW + (uint32_t)(kc * 32) + b_off);
                mma16816(cf[0], a, &b[0]);
                mma16816(cf[1], a, &b[2]);
            }
            float* po0 = out + ((size_t)t * 128 + m0f + (lane >> 2)) * 10;
            float* po1 = po0 + 80;   // +8 rows
#pragma unroll
            for (int nt = 0; nt < 2; nt++) {
                int n8 = nt * 8 + 2 * (lane & 3);
                if (n8 < 10) {
                    po0[n8] = cf[nt][0] + s_bout[n8];
                    po1[n8] = cf[nt][2] + s_bout[n8];
                }
                if (n8 + 1 < 10) {
                    po0[n8 + 1] = cf[nt][1] + s_bout[n8 + 1];
                    po1[n8 + 1] = cf[nt][3] + s_bout[n8 + 1];
                }
            }
        }
        __syncthreads();   // done reading A before next tile overwrites it
    }
}

// ---------------- launch ----------------------------------------------------
extern "C" void kernel_launch(void* const* d_in, const int* in_sizes, int n_in,
                              void* d_out, int out_size) {
    const float* x     = (const float*)d_in[0];
    const int*   idx   = (const int*)  d_in[1];
    const float* W     = (const float*)d_in[2];
    const float* b     = (const float*)d_in[3];
    const float* W_out = (const float*)d_in[4];
    const float* b_out = (const float*)d_in[5];
    float* out = (float*)d_out;

    cudaFuncSetAttribute(fused_kernel, cudaFuncAttributeMaxDynamicSharedMemorySize, DYN_SMEM);

    prep_kernel<<<769, 256>>>(idx, W, W_out, b, b_out);
    fused_kernel<<<GRID, NTHR, DYN_SMEM>>>(x, out);
}

// round 6
// speedup vs baseline: 1.1756x; 1.1756x over previous
#include <cuda_runtime.h>
#include <cuda_fp16.h>
#include <cstdint>

#define NB     131072
#define ND     256
#define NTILES 1024          // NB / 128
#define GRID   152
#define NTHR   256
#define RS     528           // smem row stride bytes (256 f16 + 8 pad) = odd*16

// dynamic smem layout
#define OFF_A   0                    // 128 rows * 528 B = 67584
#define OFF_B   67584                // 256 rows * 528 B = 135168
#define OFF_W   (67584 + 135168)     // 16 rows * 528 B = 8448
#define DYN_SMEM (67584 + 135168 + 8448)   // 211200

// ---------------- device scratch (static; no cudaMalloc) ------------------
__device__ __align__(128) __half g_Wd_img[3][256 * 264];  // pre-padded smem image
__device__ __align__(128) __half g_Wout_img[16 * 264];
__device__ float g_bias[3][256];
__device__ float g_bout[16];

// ---------------- helpers -------------------------------------------------
static __device__ __forceinline__ uint32_t smem_u32(const void* p) {
    uint32_t a;
    asm("{ .reg .u64 t; cvta.to.shared.u64 t, %1; cvt.u32.u64 %0, t; }" : "=r"(a) : "l"(p));
    return a;
}

static __device__ __forceinline__ void ldsm4(uint32_t r[4], uint32_t addr) {
    asm volatile("ldmatrix.sync.aligned.m8n8.x4.shared.b16 {%0,%1,%2,%3}, [%4];"
                 : "=r"(r[0]), "=r"(r[1]), "=r"(r[2]), "=r"(r[3]) : "r"(addr));
}

static __device__ __forceinline__ void mma16816(float c[4], const uint32_t a[4],
                                                const uint32_t b[2]) {
    asm volatile("mma.sync.aligned.m16n8k16.row.col.f32.f16.f16.f32 "
                 "{%0,%1,%2,%3}, {%4,%5,%6,%7}, {%8,%9}, {%0,%1,%2,%3};"
                 : "+f"(c[0]), "+f"(c[1]), "+f"(c[2]), "+f"(c[3])
                 : "r"(a[0]), "r"(a[1]), "r"(a[2]), "r"(a[3]), "r"(b[0]), "r"(b[1]));
}

// hardware tanh (SFU, f32): 1 MUFU op, abs err ~1e-4 or better; far more
// accurate than tanh.approx.f16x2 (which cost rel_err 9.2e-4 in R3).
static __device__ __forceinline__ float tanh_f(float z) {
    float y;
    asm("tanh.approx.f32 %0, %1;" : "=f"(y) : "f"(z));
    return y;
}

#define CP_ASYNC16(dst, src) \
    asm volatile("cp.async.cg.shared.global [%0], [%1], 16;" :: "r"(dst), "l"(src) : "memory")
#define CP_COMMIT() asm volatile("cp.async.commit_group;" ::: "memory")
#define CP_WAIT0()  asm volatile("cp.async.wait_group 0;" ::: "memory")

// ---------------- merged prep kernel --------------------------------------
__global__ void prep_kernel(const int* __restrict__ idx, const float* __restrict__ W,
                            const float* __restrict__ W_out, const float* __restrict__ b,
                            const float* __restrict__ b_out) {
    int blk = blockIdx.x;
    int t = threadIdx.x;                    // 256 = d
    if (blk < 768) {
        __shared__ int   s_i[128];
        __shared__ float s_w[128];
        int l = blk >> 8, n = blk & 255, g = n >> 6, u = n & 63;
        if (t < 128) {
            s_i[t] = idx[(l * 4 + g) * 128 + t];
            s_w[t] = W[((l * 4 + g) * 128 + t) * 64 + u];
        }
        __syncthreads();
        float sum = 0.0f;
#pragma unroll 8
        for (int k = 0; k < 128; k++)
            if (s_i[k] == t) sum += s_w[k];
        g_Wd_img[l][n * 264 + t] = __float2half(sum);
    } else {
#pragma unroll
        for (int j = 0; j < 16; j++)
            g_Wout_img[j * 264 + t] = __float2half(j < 10 ? W_out[t * 10 + j] : 0.0f);
        for (int l = 0; l < 3; l++)
            g_bias[l][t] = b[(l * 4 + (t >> 6)) * 64 + (t & 63)];
        if (t < 16) g_bout[t] = (t < 10) ? b_out[t] : 0.0f;
    }
}

// ---------------- main fused kernel ---------------------------------------
__global__ __launch_bounds__(NTHR, 1)
void fused_kernel(const float* __restrict__ x, float* __restrict__ out) {
    extern __shared__ __align__(16) char dsm[];
    char* pA = dsm + OFF_A;
    uint32_t sA = smem_u32(dsm) + OFF_A;
    uint32_t sB = smem_u32(dsm) + OFF_B;
    uint32_t sW = smem_u32(dsm) + OFF_W;

    __shared__ float s_bias[3][256];
    __shared__ float s_bout[16];

    int tid = threadIdx.x, wid = tid >> 5, lane = tid & 31;
    int lrow = lane & 7, sub = lane >> 3;
    uint32_t a_off = (uint32_t)((lrow + 8 * (sub & 1)) * RS + (sub >> 1) * 16);
    uint32_t b_off = (uint32_t)((lrow + 8 * (sub >> 1)) * RS + (sub & 1) * 16);

    int m0 = (wid >> 2) * 64;   // warp M-origin (0 or 64)
    int n0 = (wid & 3) * 64;    // warp N-origin (0,64,128,192)

    // warp-private x loader: warp wid loads rows [wid*16, wid*16+16).
    // These are exactly the rows this warp reads in the final layer, so the
    // load of tile t+1 can follow the final layer with no extra barrier.
    auto load_x = [&](int tt) {
        const float* xt = x + (size_t)tt * 128 * ND;
        int r0 = wid * 16;
#pragma unroll
        for (int r = 0; r < 16; r++) {
            int row = r0 + r;
            const float4* p = (const float4*)(xt + row * ND + lane * 8);
            float4 a = p[0], bq = p[1];
            __half2 h0 = __floats2half2_rn(a.x, a.y);
            __half2 h1 = __floats2half2_rn(a.z, a.w);
            __half2 h2 = __floats2half2_rn(bq.x, bq.y);
            __half2 h3 = __floats2half2_rn(bq.z, bq.w);
            *(uint4*)(pA + row * RS + lane * 16) =
                make_uint4(*(uint32_t*)&h0, *(uint32_t*)&h1,
                           *(uint32_t*)&h2, *(uint32_t*)&h3);
        }
    };

    // ---- one-time: biases, Wout image, B0 image, first x tile ------------
    s_bias[0][tid] = g_bias[0][tid];
    s_bias[1][tid] = g_bias[1][tid];
    s_bias[2][tid] = g_bias[2][tid];
    if (tid < 16) s_bout[tid] = g_bout[tid];
    {
        const char* wsrc = (const char*)g_Wout_img;
        for (int c = tid; c < 528; c += NTHR)            // 8448 B
            CP_ASYNC16(sW + c * 16, wsrc + c * 16);
        const char* bsrc = (const char*)g_Wd_img[0];
#pragma unroll
        for (int i = 0; i < 33; i++) {                   // 135168 B
            int c = tid + i * NTHR;
            CP_ASYNC16(sB + c * 16, bsrc + c * 16);
        }
        CP_COMMIT();
    }
    load_x(blockIdx.x);
    CP_WAIT0();
    __syncthreads();

    for (int t = blockIdx.x; t < NTILES; t += GRID) {
        // ---- 3 fused levels (x/h already in A smem) ---------------------
        for (int l = 0; l < 3; l++) {
            // GEMM: C[128x256] = A[128x256] @ Wd[l]^T  (per-warp 64x64)
            float c[4][8][4];
#pragma unroll
            for (int mt = 0; mt < 4; mt++)
#pragma unroll
                for (int nt = 0; nt < 8; nt++)
#pragma unroll
                    for (int q = 0; q < 4; q++) c[mt][nt][q] = 0.0f;

#pragma unroll
            for (int kc = 0; kc < 16; kc++) {
                uint32_t a[4][4], b[4][4];
#pragma unroll
                for (int mt = 0; mt < 4; mt++)
                    ldsm4(a[mt], sA + (uint32_t)((m0 + 16 * mt) * RS + kc * 32) + a_off);
#pragma unroll
                for (int bt = 0; bt < 4; bt++)
                    ldsm4(b[bt], sB + (uint32_t)((n0 + 16 * bt) * RS + kc * 32) + b_off);
#pragma unroll
                for (int mt = 0; mt < 4; mt++)
#pragma unroll
                    for (int nt = 0; nt < 8; nt++)
                        mma16816(c[mt][nt], a[mt], &b[nt >> 1][(nt & 1) * 2]);
            }
            __syncthreads();   // all warps done reading A and B[l]

            // prefetch next B image (l+1; at l==2 prefetch B0 for next tile)
            {
                const char* bsrc = (const char*)g_Wd_img[(l == 2) ? 0 : (l + 1)];
#pragma unroll
                for (int i = 0; i < 33; i++) {
                    int cc = tid + i * NTHR;
                    CP_ASYNC16(sB + cc * 16, bsrc + cc * 16);
                }
                CP_COMMIT();
            }

            // epilogue: bias + hw tanh -> f16, write h back into A.
            // Overlaps the async B prefetch above.
            const float* bias = s_bias[l];
#pragma unroll
            for (int mt = 0; mt < 4; mt++) {
                int row = m0 + 16 * mt + (lane >> 2);
#pragma unroll
                for (int nt = 0; nt < 8; nt++) {
                    int n = n0 + 8 * nt + 2 * (lane & 3);
                    float b0v = bias[n], b1v = bias[n + 1];
                    float y0 = tanh_f(c[mt][nt][0] + b0v);
                    float y1 = tanh_f(c[mt][nt][1] + b1v);
                    float y2 = tanh_f(c[mt][nt][2] + b0v);
                    float y3 = tanh_f(c[mt][nt][3] + b1v);
                    __half2 h01 = __floats2half2_rn(y0, y1);
                    __half2 h23 = __floats2half2_rn(y2, y3);
                    *(uint32_t*)(pA + row * RS + n * 2)       = *(uint32_t*)&h01;
                    *(uint32_t*)(pA + (row + 8) * RS + n * 2) = *(uint32_t*)&h23;
                }
            }
            CP_WAIT0();
            __syncthreads();   // h visible + next B visible
        }

        // ---- final layer: out = h3 @ W_out + b_out (warp-per-16-rows) ---
        {
            float cf[2][4];
#pragma unroll
            for (int nt = 0; nt < 2; nt++)
#pragma unroll
                for (int q = 0; q < 4; q++) cf[nt][q] = 0.0f;
            int m0f = wid * 16;
#pragma unroll
            for (int kc = 0; kc < 16; kc++) {
                uint32_t a[4], b[4];
                ldsm4(a, sA + (uint32_t)(m0f * RS + kc * 32) + a_off);
                ldsm4(b, sW + (uint32_t)(kc * 32) + b_off);
                mma16816(cf[0], a, &b[0]);
                mma16816(cf[1], a, &b[2]);
            }
            float* po0 = out + ((size_t)t * 128 + m0f + (lane >> 2)) * 10;
            float* po1 = po0 + 80;   // +8 rows
#pragma unroll
            for (int nt = 0; nt < 2; nt++) {
                int n8 = nt * 8 + 2 * (lane & 3);
                if (n8 < 10) {
                    po0[n8] = cf[nt][0] + s_bout[n8];
                    po1[n8] = cf[nt][2] + s_bout[n8];
                }
                if (n8 + 1 < 10) {
                    po0[n8 + 1] = cf[nt][1] + s_bout[n8 + 1];
                    po1[n8 + 1] = cf[nt][3] + s_bout[n8 + 1];
                }
            }
        }

        // ---- load next x tile into this warp's private rows -------------
        // Safe without a barrier: this warp only overwrites rows it alone
        // read in the final layer. The level-0 entry barrier (end of the
        // CP_WAIT0/sync in the last level iteration of the next pass) orders
        // it for everyone else.
        if (t + GRID < NTILES) load_x(t + GRID);
        __syncthreads();   // x visible to all warps before next tile GEMM
    }
}

// ---------------- launch ----------------------------------------------------
extern "C" void kernel_launch(void* const* d_in, const int* in_sizes, int n_in,
                              void* d_out, int out_size) {
    const float* x     = (const float*)d_in[0];
    const int*   idx   = (const int*)  d_in[1];
    const float* W     = (const float*)d_in[2];
    const float* b     = (const float*)d_in[3];
    const float* W_out = (const float*)d_in[4];
    const float* b_out = (const float*)d_in[5];
    float* out = (float*)d_out;

    cudaFuncSetAttribute(fused_kernel, cudaFuncAttributeMaxDynamicSharedMemorySize, DYN_SMEM);

    prep_kernel<<<769, 256>>>(idx, W, W_out, b, b_out);
    fused_kernel<<<GRID, NTHR, DYN_SMEM>>>(x, out);
}